// round 2
// baseline (speedup 1.0000x reference)
#include <cuda_runtime.h>
#include <math.h>

#define T_ENC  40
#define HID    128
#define DIN    512
#define STATE  256
#define ACT    18
#define BATCHN 1024

// Shared memory layout (bytes):
//  divm   : 40 * 8        = 320
//  wrT    : 128*129*4     = 66048   (w_rec transposed, padded)
//  wa     : 18*129*4      = 9288    (w_actor, padded rows)
//  wc     : 128*4         = 512
//  G      : 40*128*4      = 20480   (period-group input sums)
//  per    : 512*4         = 2048
//  msk    : 4*4           = 16
//  ms     : 19*4          = 76
#define SMEM_BYTES 98788

__global__ void __launch_bounds__(128, 2)
snn_kernel(const float* __restrict__ x,
           const float* __restrict__ w_in,
           const float* __restrict__ w_rec,
           const float* __restrict__ w_actor,
           const float* __restrict__ w_critic,
           float* __restrict__ out)
{
    extern __shared__ unsigned char sraw[];
    unsigned long long* divm = (unsigned long long*)sraw;          // 40
    float* wrT = (float*)(sraw + 320);                             // 128*129
    float* wa  = wrT + 128 * 129;                                  // 18*129
    float* wc  = wa  + ACT * 129;                                  // 128
    float* G   = wc  + 128;                                        // 40*128
    int*   per = (int*)(G + 40 * HID);                             // 512
    unsigned* msk = (unsigned*)(per + DIN);                        // 4
    float* ms  = (float*)(msk + 4);                                // 19

    const int tid = threadIdx.x;
    const int b   = blockIdx.x;

    // ---- stage w_rec transposed: wrT[j*129 + h] = w_rec[h*128 + j] ----
    // (thread tid = j; loop r = h; coalesced global read, conflict-free STS)
    #pragma unroll 4
    for (int r = 0; r < HID; ++r)
        wrT[tid * 129 + r] = w_rec[r * HID + tid];

    // ---- stage w_actor (padded) + w_critic ----
    for (int idx = tid; idx < ACT * HID; idx += 128)
        wa[(idx / HID) * 129 + (idx % HID)] = w_actor[idx];
    wc[tid] = w_critic[tid];

    // ---- divisor masks: bit (k-1) set iff k divides (t+1) ----
    if (tid < T_ENC) {
        unsigned long long m = 0ull;
        int n = tid + 1;
        for (int k = 1; k <= T_ENC; ++k)
            if (n % k == 0) m |= 1ull << (k - 1);
        divm[tid] = m;
    }
    if (tid < 4) msk[tid] = 0u;

    // ---- zero G ----
    for (int idx = tid; idx < T_ENC * HID; idx += 128) G[idx] = 0.f;

    // ---- encoder: compute spike period per concatenated feature ----
    // Bit-exact 40-step simulation of the constant-current LIF.
    for (int q = 0; q < 4; ++q) {
        int d = q * 128 + tid;
        float xv = x[b * STATE + (d & 255)];
        float c  = 50.f * xv;
        float I  = (d < 256) ? fmaxf(c, 0.f) : fmaxf(-c, 0.f);
        int p = 0;
        float v = 0.f;
        #pragma unroll 1
        for (int s = 1; s <= T_ENC; ++s) {
            v = v + 0.1f * (I - v);
            if (v - 1.0f > 0.0f) { p = s; break; }
        }
        per[d] = p;
    }
    __syncthreads();

    // ---- build period-group sums G[k-1][h] = sum_{d: period==k} w_in[h][d] ----
    {
        const float* wrow = w_in + tid * DIN;
        float r1 = 0.f, r2 = 0.f, r3 = 0.f;
        #pragma unroll 4
        for (int d0 = 0; d0 < DIN; d0 += 4) {
            int k0 = per[d0], k1 = per[d0 + 1], k2 = per[d0 + 2], k3 = per[d0 + 3];
            float w0 = 0.f, w1 = 0.f, w2 = 0.f, w3 = 0.f;
            if (k0) w0 = __ldg(wrow + d0);
            if (k1) w1 = __ldg(wrow + d0 + 1);
            if (k2) w2 = __ldg(wrow + d0 + 2);
            if (k3) w3 = __ldg(wrow + d0 + 3);
            if (k0 == 1) r1 += w0; else if (k0 == 2) r2 += w0; else if (k0 == 3) r3 += w0; else if (k0) G[(k0 - 1) * HID + tid] += w0;
            if (k1 == 1) r1 += w1; else if (k1 == 2) r2 += w1; else if (k1 == 3) r3 += w1; else if (k1) G[(k1 - 1) * HID + tid] += w1;
            if (k2 == 1) r1 += w2; else if (k2 == 2) r2 += w2; else if (k2 == 3) r3 += w2; else if (k2) G[(k2 - 1) * HID + tid] += w2;
            if (k3 == 1) r1 += w3; else if (k3 == 2) r2 += w3; else if (k3 == 3) r3 += w3; else if (k3) G[(k3 - 1) * HID + tid] += w3;
        }
        G[0 * HID + tid] = r1;
        G[1 * HID + tid] = r2;
        G[2 * HID + tid] = r3;
    }
    __syncthreads();

    // ---- main 40-step recurrence ----
    float v  = 0.f, ci = 0.f;                 // hidden LIF state (per h = tid)
    float va = 0.f, ia = 0.f;                 // readout LI state (lanes 0..18)
    float mmax = -INFINITY;
    const float* wrow_ro = (tid < ACT) ? (wa + tid * 129) : wc;
    const float* col = wrT + tid;

    for (int t = 0; t < T_ENC; ++t) {
        // LIF dynamics (mirror reference op order)
        float vdec = v + 0.1f * (ci - v);
        float idec = ci - 0.2f * ci;
        bool  sp   = (vdec - 1.0f) > 0.0f;
        v = sp ? 0.f : vdec;

        // recurrent input from OLD spikes (masks currently hold z_{t-1})
        float rec0 = 0.f, rec1 = 0.f;
        {
            unsigned m;
            m = msk[0]; while (m) { int j = __ffs(m) - 1; m &= m - 1; rec0 += col[j * 129]; }
            m = msk[1]; while (m) { int j = __ffs(m) - 1; m &= m - 1; rec1 += col[(32 + j) * 129]; }
            m = msk[2]; while (m) { int j = __ffs(m) - 1; m &= m - 1; rec0 += col[(64 + j) * 129]; }
            m = msk[3]; while (m) { int j = __ffs(m) - 1; m &= m - 1; rec1 += col[(96 + j) * 129]; }
        }

        // encoded input current: sum of period groups whose period divides (t+1)
        float inp = 0.f;
        {
            unsigned long long dm = divm[t];
            while (dm) { int kk = __ffsll(dm) - 1; dm &= dm - 1; inp += G[kk * HID + tid]; }
        }

        __syncthreads();  // all reads of old masks complete

        unsigned bal = __ballot_sync(0xffffffffu, sp);
        if ((tid & 31) == 0) msk[tid >> 5] = bal;

        __syncthreads();  // new masks (z_t) visible

        // actor/critic readouts use NEW spikes z_t
        if (tid < ACT + 1) {
            float nva = va + 0.1f * (ia - va);   // uses pre-update ia
            float dot0 = 0.f, dot1 = 0.f;
            unsigned m;
            m = msk[0]; while (m) { int j = __ffs(m) - 1; m &= m - 1; dot0 += wrow_ro[j]; }
            m = msk[1]; while (m) { int j = __ffs(m) - 1; m &= m - 1; dot1 += wrow_ro[32 + j]; }
            m = msk[2]; while (m) { int j = __ffs(m) - 1; m &= m - 1; dot0 += wrow_ro[64 + j]; }
            m = msk[3]; while (m) { int j = __ffs(m) - 1; m &= m - 1; dot1 += wrow_ro[96 + j]; }
            ia = (ia - 0.2f * ia) + (dot0 + dot1);
            va = nva;
            mmax = fmaxf(mmax, nva);
        }

        ci = idec + inp + (rec0 + rec1);
    }

    if (tid < ACT + 1) ms[tid] = mmax;
    __syncthreads();

    // ---- softmax (18 actions) + critic writeout ----
    if (tid == 0) {
        float mx = -INFINITY;
        #pragma unroll
        for (int a = 0; a < ACT; ++a) mx = fmaxf(mx, ms[a]);
        float e[ACT];
        float s = 0.f;
        #pragma unroll
        for (int a = 0; a < ACT; ++a) { e[a] = expf(ms[a] - mx); s += e[a]; }
        float inv = 1.f / s;
        #pragma unroll
        for (int a = 0; a < ACT; ++a) out[b * ACT + a] = e[a] * inv;
        out[BATCHN * ACT + b] = ms[ACT];
    }
}

extern "C" void kernel_launch(void* const* d_in, const int* in_sizes, int n_in,
                              void* d_out, int out_size)
{
    const float* x        = (const float*)d_in[0];
    const float* w_in     = (const float*)d_in[1];
    const float* w_rec    = (const float*)d_in[2];
    const float* w_actor  = (const float*)d_in[3];
    const float* w_critic = (const float*)d_in[4];
    float* out = (float*)d_out;

    cudaFuncSetAttribute(snn_kernel, cudaFuncAttributeMaxDynamicSharedMemorySize, SMEM_BYTES);
    snn_kernel<<<BATCHN, 128, SMEM_BYTES>>>(x, w_in, w_rec, w_actor, w_critic, out);
}

// round 4
// speedup vs baseline: 3.4078x; 3.4078x over previous
#include <cuda_runtime.h>
#include <math.h>

#define T_ENC   40
#define HID     128
#define DIN     512
#define STATE   256
#define ACT     18
#define BATCHN  1024
#define ROWS    7
#define KMAX_G  20
#define SLOW_CAP 64

struct RowSmem {
    float    G[KMAX_G * HID];   // 10240 B : period-group sums, k=1..20
    int      per[DIN];          // 2048  B : spike period per feature (0 = never)
    int      lst[2][132];       // 1056  B : double-buffered compacted spike lists (padded)
    unsigned msk[4];            // 16
    int      cnt4[2];           // 8       : padded list lengths
    int      ns;                // 4       : slow-list count
    int      _p0;               // 4
    unsigned slow[SLOW_CAP];    // 256     : (d | k<<16) for k in 21..40
    float    ms[20];            // 80      : per-readout-lane max voltage
};  // 13712 B, 16-aligned

struct Shm {
    float    wrT[129 * HID];    // 66048 B : w_rec transposed, row 128 = zeros
    float    wa[19 * 129 + 1];  // 9808  B : actor rows 0..17 + critic row 18, col 128 = 0
    unsigned divm[T_ENC];       // 160   B : divisor masks (k<=20)
    RowSmem  row[ROWS];         // 95984 B
};  // ~171 KB

#define RBAR(r) asm volatile("bar.sync %0, %1;" :: "r"((r) + 1), "r"(128) : "memory")

__global__ void __launch_bounds__(ROWS * HID, 1)
snn_kernel(const float* __restrict__ x,
           const float* __restrict__ w_in,
           const float* __restrict__ w_rec,
           const float* __restrict__ w_actor,
           const float* __restrict__ w_critic,
           float* __restrict__ out)
{
    extern __shared__ unsigned char sraw[];
    Shm* S = (Shm*)sraw;

    const int tid = threadIdx.x;
    const int row = tid >> 7;
    const int h   = tid & 127;
    const int b   = blockIdx.x * ROWS + row;

    // ---- CTA-cooperative staging ----
    for (int i = tid; i < 129 * HID; i += ROWS * HID) {
        int j = i >> 7, hh = i & 127;
        S->wrT[i] = (j < 128) ? w_rec[hh * HID + j] : 0.f;
    }
    for (int i = tid; i < 19 * 129; i += ROWS * HID) {
        int a = i / 129, j = i - a * 129;
        float v = 0.f;
        if (j < 128) v = (a < ACT) ? w_actor[a * HID + j] : w_critic[j];
        S->wa[i] = v;
    }
    if (tid < T_ENC) {
        unsigned m = 0u;
        int n = tid + 1;
        #pragma unroll
        for (int k = 1; k <= KMAX_G; ++k)
            if (n % k == 0) m |= 1u << (k - 1);
        S->divm[tid] = m;
    }
    __syncthreads();

    if (b >= BATCHN) return;                 // no CTA-wide syncs after this point

    RowSmem& R = S->row[row];

    if (h == 0) { R.ns = 0; R.cnt4[0] = 0; }
    #pragma unroll
    for (int k = 0; k < KMAX_G; ++k) R.G[k * HID + h] = 0.f;
    RBAR(row);

    // ---- encoder periods (bit-exact constant-current LIF) ----
    #pragma unroll
    for (int q = 0; q < 4; ++q) {
        int d = q * HID + h;
        float xv = x[b * STATE + (d & 255)];
        float c  = 50.f * xv;
        float I  = (d < 256) ? fmaxf(c, 0.f) : fmaxf(-c, 0.f);
        int p = 0;
        float v = 0.f;
        #pragma unroll 1
        for (int s = 1; s <= T_ENC; ++s) {
            v = v + 0.1f * (I - v);
            if (v - 1.0f > 0.0f) { p = s; break; }
        }
        R.per[d] = p;
        if (p > KMAX_G) {
            int slot = atomicAdd(&R.ns, 1);
            if (slot < SLOW_CAP) R.slow[slot] = (unsigned)d | ((unsigned)p << 16);
        }
    }
    RBAR(row);
    if (h == 0) {                            // deterministic order: sort slow list by d
        int n = R.ns; if (n > SLOW_CAP) n = SLOW_CAP;
        for (int i = 1; i < n; ++i) {
            unsigned key = R.slow[i];
            int j = i - 1;
            while (j >= 0 && (R.slow[j] & 0xffffu) > (key & 0xffffu)) { R.slow[j + 1] = R.slow[j]; --j; }
            R.slow[j + 1] = key;
        }
        R.ns = n;
    }
    RBAR(row);
    const int ns = R.ns;

    // ---- build G (d-ascending per (h,k): deterministic) ----
    {
        const float4* wrow = (const float4*)(w_in + h * DIN);
        float r1 = 0.f, r2 = 0.f, r3 = 0.f;
        #pragma unroll 4
        for (int d0 = 0; d0 < DIN; d0 += 4) {
            float4 w = __ldg(&wrow[d0 >> 2]);
            int4 kk = *(const int4*)&R.per[d0];
            if (kk.x == 1) r1 += w.x; else if (kk.x == 2) r2 += w.x; else if (kk.x == 3) r3 += w.x; else if (kk.x >= 4 && kk.x <= KMAX_G) R.G[(kk.x - 1) * HID + h] += w.x;
            if (kk.y == 1) r1 += w.y; else if (kk.y == 2) r2 += w.y; else if (kk.y == 3) r3 += w.y; else if (kk.y >= 4 && kk.y <= KMAX_G) R.G[(kk.y - 1) * HID + h] += w.y;
            if (kk.z == 1) r1 += w.z; else if (kk.z == 2) r2 += w.z; else if (kk.z == 3) r3 += w.z; else if (kk.z >= 4 && kk.z <= KMAX_G) R.G[(kk.z - 1) * HID + h] += w.z;
            if (kk.w == 1) r1 += w.w; else if (kk.w == 2) r2 += w.w; else if (kk.w == 3) r3 += w.w; else if (kk.w >= 4 && kk.w <= KMAX_G) R.G[(kk.w - 1) * HID + h] += w.w;
        }
        R.G[0 * HID + h] = r1;
        R.G[1 * HID + h] = r2;
        R.G[2 * HID + h] = r3;
    }
    // (each thread only ever reads its own G column -> no barrier needed)

    // ---- main 40-step recurrence ----
    float v = 0.f, ci = 0.f, va = 0.f, ia = 0.f;
    float mmax = -INFINITY;
    const int myw = h >> 5;
    const unsigned lanelt = (1u << (h & 31)) - 1u;

    #pragma unroll 1
    for (int t = 0; t < T_ENC; ++t) {
        const int p = t & 1;

        // --- phase A: dynamics, ballot, gather over OLD spikes ---
        float vdec = v + 0.1f * (ci - v);
        float idec = ci - 0.2f * ci;
        bool  sp   = (vdec - 1.0f) > 0.0f;
        v = sp ? 0.f : vdec;

        unsigned bal = __ballot_sync(0xffffffffu, sp);
        if ((h & 31) == 0) R.msk[myw] = bal;

        float a0 = 0.f, a1 = 0.f, a2 = 0.f, a3 = 0.f;
        {
            int n4 = R.cnt4[p];
            #pragma unroll 1
            for (int i = 0; i < n4; i += 4) {
                int4 jj = *(const int4*)&R.lst[p][i];
                a0 += S->wrT[jj.x * HID + h];
                a1 += S->wrT[jj.y * HID + h];
                a2 += S->wrT[jj.z * HID + h];
                a3 += S->wrT[jj.w * HID + h];
            }
        }
        float inp = 0.f;
        {
            unsigned dm = S->divm[t];
            while (dm) { int kk = __ffs(dm) - 1; dm &= dm - 1; inp += R.G[kk * HID + h]; }
            for (int e = 0; e < ns; ++e) {
                unsigned pk = R.slow[e];
                if ((int)(pk >> 16) == t + 1) inp += __ldg(w_in + h * DIN + (pk & 0xffffu));
            }
        }
        ci = idec + inp + ((a0 + a1) + (a2 + a3));
        RBAR(row);

        // --- phase B: compact NEW spike list ---
        {
            unsigned m0 = R.msk[0], m1 = R.msk[1], m2 = R.msk[2], m3 = R.msk[3];
            int cnt = __popc(m0) + __popc(m1) + __popc(m2) + __popc(m3);
            if (sp) {
                int r_  = __popc(bal & lanelt);
                int off = 0;
                if (myw > 0) off += __popc(m0);
                if (myw > 1) off += __popc(m1);
                if (myw > 2) off += __popc(m2);
                R.lst[p ^ 1][off + r_] = h;
            }
            if (h == 0) {
                int npad = (-cnt) & 3;
                for (int q = 0; q < npad; ++q) R.lst[p ^ 1][cnt + q] = 128;
                R.cnt4[p ^ 1] = cnt + npad;
            }
        }
        RBAR(row);

        // --- phase C: actor/critic readout over NEW spikes ---
        if (h < ACT + 1) {
            float nva = va + 0.1f * (ia - va);
            float d0 = 0.f, d1 = 0.f, d2 = 0.f, d3 = 0.f;
            int n4n = R.cnt4[p ^ 1];
            const float* wrow = &S->wa[h * 129];
            #pragma unroll 1
            for (int i = 0; i < n4n; i += 4) {
                int4 jj = *(const int4*)&R.lst[p ^ 1][i];
                d0 += wrow[jj.x]; d1 += wrow[jj.y]; d2 += wrow[jj.z]; d3 += wrow[jj.w];
            }
            ia = (ia - 0.2f * ia) + ((d0 + d1) + (d2 + d3));
            va = nva;
            mmax = fmaxf(mmax, nva);
        }
    }

    if (h < ACT + 1) R.ms[h] = mmax;
    RBAR(row);

    if (h == 0) {
        float mx = -INFINITY;
        #pragma unroll
        for (int a = 0; a < ACT; ++a) mx = fmaxf(mx, R.ms[a]);
        float e[ACT], s = 0.f;
        #pragma unroll
        for (int a = 0; a < ACT; ++a) { e[a] = expf(R.ms[a] - mx); s += e[a]; }
        float inv = 1.f / s;
        #pragma unroll
        for (int a = 0; a < ACT; ++a) out[b * ACT + a] = e[a] * inv;
        out[BATCHN * ACT + b] = R.ms[ACT];
    }
}

extern "C" void kernel_launch(void* const* d_in, const int* in_sizes, int n_in,
                              void* d_out, int out_size)
{
    const float* x        = (const float*)d_in[0];
    const float* w_in     = (const float*)d_in[1];
    const float* w_rec    = (const float*)d_in[2];
    const float* w_actor  = (const float*)d_in[3];
    const float* w_critic = (const float*)d_in[4];
    float* out = (float*)d_out;

    cudaFuncSetAttribute(snn_kernel, cudaFuncAttributeMaxDynamicSharedMemorySize, (int)sizeof(Shm));
    int grid = (BATCHN + ROWS - 1) / ROWS;
    snn_kernel<<<grid, ROWS * HID, sizeof(Shm)>>>(x, w_in, w_rec, w_actor, w_critic, out);
}

// round 5
// speedup vs baseline: 4.9465x; 1.4515x over previous
#include <cuda_runtime.h>
#include <math.h>

#define T_ENC   40
#define HID     128
#define DIN     512
#define STATE   256
#define ACT     18
#define BATCHN  1024
#define ROWS    7
#define KMAX_G  20
#define SLOW_CAP 64

// Transposed w_in: w_inT[d*128 + h] = w_in[h*512 + d]
__device__ float g_winT[DIN * HID];

struct __align__(16) RowSmem {
    float    G[KMAX_G * HID];   // 10240 B
    int      per[DIN];          // 2048  B
    int      lst[2][132];       // 1056  B (16B-aligned, padded to mult of 4)
    unsigned msk[2][4];         // 32    B (double-buffered ballots)
    int      cnt4[2];           // 8
    int      ns;                // 4
    int      _p0;               // 4
    unsigned slow[SLOW_CAP];    // 256
    float    ms[20];            // 80
};  // 13728 B

struct Shm {
    float    wrT[129 * HID];    // 66048 B : w_rec^T (row 128 = zeros); ALSO chunk buffer in prologue
    float    wa[19 * 129 + 1];  // 9808  B : actor rows 0..17 + critic row 18, col 128 = 0
    unsigned divm[T_ENC];       // 160   B
    RowSmem  row[ROWS];         // 96096 B
};  // ~172 KB

#define RBAR(r) asm volatile("bar.sync %0, %1;" :: "r"((r) + 1), "r"(128) : "memory")

__global__ void transpose_win(const float* __restrict__ w_in) {
    int i = blockIdx.x * blockDim.x + threadIdx.x;   // 65536 elements
    int h = i >> 9, d = i & 511;
    g_winT[d * HID + h] = w_in[i];
}

__global__ void __launch_bounds__(ROWS * HID, 1)
snn_kernel(const float* __restrict__ x,
           const float* __restrict__ w_in,
           const float* __restrict__ w_rec,
           const float* __restrict__ w_actor,
           const float* __restrict__ w_critic,
           float* __restrict__ out)
{
    extern __shared__ unsigned char sraw[];
    Shm* S = (Shm*)sraw;

    const int tid = threadIdx.x;
    const int row = tid >> 7;
    const int h   = tid & 127;
    int b = blockIdx.x * ROWS + row;
    const bool active = (b < BATCHN);
    if (!active) b = BATCHN - 1;             // clamp; garbage compute, no output

    // ---- stage w_actor/w_critic (padded) + divisor masks ----
    for (int i = tid; i < 19 * 129; i += ROWS * HID) {
        int a = i / 129, j = i - a * 129;
        float v = 0.f;
        if (j < 128) v = (a < ACT) ? w_actor[a * HID + j] : w_critic[j];
        S->wa[i] = v;
    }
    if (tid < T_ENC) {
        unsigned m = 0u;
        int n = tid + 1;
        #pragma unroll
        for (int k = 1; k <= KMAX_G; ++k)
            if (n % k == 0) m |= 1u << (k - 1);
        S->divm[tid] = m;
    }

    RowSmem& R = S->row[row];
    if (h == 0) { R.ns = 0; R.cnt4[0] = 0; R.cnt4[1] = 0; }
    #pragma unroll
    for (int k = 0; k < KMAX_G; ++k) R.G[k * HID + h] = 0.f;
    RBAR(row);

    // ---- encoder periods (bit-exact constant-current LIF sim) ----
    #pragma unroll
    for (int q = 0; q < 4; ++q) {
        int d = q * HID + h;
        float xv = x[b * STATE + (d & 255)];
        float c  = 50.f * xv;
        float I  = (d < 256) ? fmaxf(c, 0.f) : fmaxf(-c, 0.f);
        int p = 0;
        float v = 0.f;
        #pragma unroll 1
        for (int s = 1; s <= T_ENC; ++s) {
            v = v + 0.1f * (I - v);
            if (v - 1.0f > 0.0f) { p = s; break; }
        }
        R.per[d] = p;
        if (p > KMAX_G) {
            int slot = atomicAdd(&R.ns, 1);
            if (slot < SLOW_CAP) R.slow[slot] = (unsigned)d | ((unsigned)p << 16);
        }
    }
    RBAR(row);
    if (h == 0) {                            // deterministic order: sort slow list by d
        int n = R.ns; if (n > SLOW_CAP) n = SLOW_CAP;
        for (int i = 1; i < n; ++i) {
            unsigned key = R.slow[i];
            int j = i - 1;
            while (j >= 0 && (R.slow[j] & 0xffffu) > (key & 0xffffu)) { R.slow[j + 1] = R.slow[j]; --j; }
            R.slow[j + 1] = key;
        }
        R.ns = n;
    }
    __syncthreads();
    const int ns = R.ns;

    // ---- G build: stream w_inT through smem in 4 chunks (shared by all 7 rows) ----
    {
        float r1 = 0.f, r2 = 0.f, r3 = 0.f;
        for (int c = 0; c < 4; ++c) {
            // coalesced linear copy of w_inT rows [c*128, c*128+128) into wrT space
            const float4* src = (const float4*)(g_winT + c * 128 * HID);
            float4* dst = (float4*)S->wrT;
            #pragma unroll 2
            for (int i = tid; i < (128 * HID) / 4; i += ROWS * HID) dst[i] = src[i];
            __syncthreads();

            const int* perc = &R.per[c * 128];
            #pragma unroll 4
            for (int dd = 0; dd < 128; dd += 4) {
                int4 kk = *(const int4*)&perc[dd];   // warp-uniform (per-row data)
                if (kk.x) { float w = S->wrT[(dd + 0) * HID + h]; if (kk.x == 1) r1 += w; else if (kk.x == 2) r2 += w; else if (kk.x == 3) r3 += w; else if (kk.x <= KMAX_G) R.G[(kk.x - 1) * HID + h] += w; }
                if (kk.y) { float w = S->wrT[(dd + 1) * HID + h]; if (kk.y == 1) r1 += w; else if (kk.y == 2) r2 += w; else if (kk.y == 3) r3 += w; else if (kk.y <= KMAX_G) R.G[(kk.y - 1) * HID + h] += w; }
                if (kk.z) { float w = S->wrT[(dd + 2) * HID + h]; if (kk.z == 1) r1 += w; else if (kk.z == 2) r2 += w; else if (kk.z == 3) r3 += w; else if (kk.z <= KMAX_G) R.G[(kk.z - 1) * HID + h] += w; }
                if (kk.w) { float w = S->wrT[(dd + 3) * HID + h]; if (kk.w == 1) r1 += w; else if (kk.w == 2) r2 += w; else if (kk.w == 3) r3 += w; else if (kk.w <= KMAX_G) R.G[(kk.w - 1) * HID + h] += w; }
            }
            __syncthreads();                 // chunk consumed before next overwrite
        }
        R.G[0 * HID + h] = r1;
        R.G[1 * HID + h] = r2;
        R.G[2 * HID + h] = r3;
    }

    // ---- stage w_rec transposed (overwrites chunk buffer) ----
    for (int i = tid; i < 129 * HID; i += ROWS * HID) {
        int j = i >> 7, hh = i & 127;
        S->wrT[i] = (j < 128) ? w_rec[hh * HID + j] : 0.f;
    }
    __syncthreads();
    if (!active) return;                     // only named barriers remain

    // ---- main 40-step recurrence: ONE barrier per step, deferred merged readout ----
    float v = 0.f, ci = 0.f, va = 0.f, ia = 0.f;
    float mmax = -INFINITY;
    const int myw = h >> 5;
    const unsigned lanelt = (1u << (h & 31)) - 1u;
    const bool rolane = (h < ACT + 1);
    const float* wrow_a = &S->wa[h * 129];   // valid reads only used when rolane
    int cur = 0;                             // lst[cur] holds z_{t-1} (empty at t=0)

    #pragma unroll 1
    for (int t = 0; t < T_ENC; ++t) {
        // dynamics + ballot (z_t)
        float vdec = v + 0.1f * (ci - v);
        float idec = ci - 0.2f * ci;
        bool  sp   = (vdec - 1.0f) > 0.0f;
        v = sp ? 0.f : vdec;

        unsigned bal = __ballot_sync(0xffffffffu, sp);
        const int pb = t & 1;
        if ((h & 31) == 0) R.msk[pb][myw] = bal;
        RBAR(row);

        // compact z_t into lst[cur^1]
        {
            unsigned m0 = R.msk[pb][0], m1 = R.msk[pb][1], m2 = R.msk[pb][2], m3 = R.msk[pb][3];
            int cnt = __popc(m0) + __popc(m1) + __popc(m2) + __popc(m3);
            if (sp) {
                int r_  = __popc(bal & lanelt);
                int off = 0;
                if (myw > 0) off += __popc(m0);
                if (myw > 1) off += __popc(m1);
                if (myw > 2) off += __popc(m2);
                R.lst[cur ^ 1][off + r_] = h;
            }
            if (h == 0) {
                int npad = (-cnt) & 3;
                #pragma unroll
                for (int q = 0; q < 3; ++q) if (q < npad) R.lst[cur ^ 1][cnt + q] = 128;
                R.cnt4[cur ^ 1] = cnt + npad;
            }
        }

        // gather recurrent over z_{t-1} (lst[cur]); lanes<19 also accumulate deferred readout
        float a0 = 0.f, a1 = 0.f, a2 = 0.f, a3 = 0.f;
        float d0 = 0.f, d1 = 0.f, d2 = 0.f, d3 = 0.f;
        {
            int n4 = R.cnt4[cur];
            #pragma unroll 1
            for (int i = 0; i < n4; i += 4) {
                int4 jj = *(const int4*)&R.lst[cur][i];
                a0 += S->wrT[jj.x * HID + h];
                a1 += S->wrT[jj.y * HID + h];
                a2 += S->wrT[jj.z * HID + h];
                a3 += S->wrT[jj.w * HID + h];
                if (rolane) {
                    d0 += wrow_a[jj.x]; d1 += wrow_a[jj.y];
                    d2 += wrow_a[jj.z]; d3 += wrow_a[jj.w];
                }
            }
        }

        // encoded input current
        float inp = 0.f;
        {
            unsigned dm = S->divm[t];
            while (dm) { int kk = __ffs(dm) - 1; dm &= dm - 1; inp += R.G[kk * HID + h]; }
            for (int e = 0; e < ns; ++e) {
                unsigned pk = R.slow[e];
                if ((int)(pk >> 16) == t + 1) inp += g_winT[(pk & 0xffffu) * HID + h];
            }
        }

        // deferred readout state update: applies z_{t-1} (skip at t=0: no z_{-1})
        if (rolane && t > 0) {
            float nva = va + 0.1f * (ia - va);
            ia = (ia - 0.2f * ia) + ((d0 + d1) + (d2 + d3));
            va = nva;
            mmax = fmaxf(mmax, nva);
        }

        ci = idec + inp + ((a0 + a1) + (a2 + a3));
        cur ^= 1;
    }

    // final readout update for z_{T-1}
    RBAR(row);
    if (rolane) {
        float nva = va + 0.1f * (ia - va);
        float d0 = 0.f, d1 = 0.f, d2 = 0.f, d3 = 0.f;
        int n4 = R.cnt4[cur];
        #pragma unroll 1
        for (int i = 0; i < n4; i += 4) {
            int4 jj = *(const int4*)&R.lst[cur][i];
            d0 += wrow_a[jj.x]; d1 += wrow_a[jj.y];
            d2 += wrow_a[jj.z]; d3 += wrow_a[jj.w];
        }
        (void)d0; (void)d1; (void)d2; (void)d3;   // ia would be updated, but never read again
        mmax = fmaxf(mmax, nva);
        R.ms[h] = mmax;
    }
    RBAR(row);

    if (h == 0) {
        float mx = -INFINITY;
        #pragma unroll
        for (int a = 0; a < ACT; ++a) mx = fmaxf(mx, R.ms[a]);
        float e[ACT], s = 0.f;
        #pragma unroll
        for (int a = 0; a < ACT; ++a) { e[a] = expf(R.ms[a] - mx); s += e[a]; }
        float inv = 1.f / s;
        #pragma unroll
        for (int a = 0; a < ACT; ++a) out[b * ACT + a] = e[a] * inv;
        out[BATCHN * ACT + b] = R.ms[ACT];
    }
}

extern "C" void kernel_launch(void* const* d_in, const int* in_sizes, int n_in,
                              void* d_out, int out_size)
{
    const float* x        = (const float*)d_in[0];
    const float* w_in     = (const float*)d_in[1];
    const float* w_rec    = (const float*)d_in[2];
    const float* w_actor  = (const float*)d_in[3];
    const float* w_critic = (const float*)d_in[4];
    float* out = (float*)d_out;

    transpose_win<<<256, 256>>>(w_in);

    cudaFuncSetAttribute(snn_kernel, cudaFuncAttributeMaxDynamicSharedMemorySize, (int)sizeof(Shm));
    int grid = (BATCHN + ROWS - 1) / ROWS;
    snn_kernel<<<grid, ROWS * HID, sizeof(Shm)>>>(x, w_in, w_rec, w_actor, w_critic, out);
}